// round 10
// baseline (speedup 1.0000x reference)
#include <cuda_runtime.h>
#include <cuda_fp16.h>

#define NODES_MAX 100000
#define EDGES_MAX 1000000
#define HID 64

// fixed-point scale for degree accumulation (packed with count in u64)
#define DEG_FX 67108864.0f           // 2^26
#define DEG_FX_INV (1.0f / 67108864.0f)
#define CNT_SHIFT 40
#define DEG_MASK ((1ull << CNT_SHIFT) - 1ull)

// Scratch (allocation-free rule: __device__ globals)
__device__ unsigned long long g_deg64[NODES_MAX];
__device__ float  g_dinv[NODES_MAX];
__device__ int    g_cnt [NODES_MAX];
__device__ int    g_off [NODES_MAX];
__device__ int    g_cur [NODES_MAX];
__device__ int    g_bsum[256];
__device__ int2   g_csr [EDGES_MAX];
__device__ __half g_h  [(size_t)NODES_MAX * HID];   // fp16 projected features
__device__ float  g_mid[(size_t)NODES_MAX * HID];   // layer-1 output (fp32)

#define FMA_F32X2(d, a, b) \
    asm("fma.rn.f32x2 %0, %1, %2, %0;" : "+l"(d) : "l"(a), "l"(b))
#define PACK_F32X2(out, lo, hi) \
    asm("mov.b64 %0, {%1, %2};" : "=l"(out) : "f"(lo), "f"(hi))
#define UNPACK_F32X2(lo, hi, in) \
    asm("mov.b64 {%0, %1}, %2;" : "=f"(lo), "=f"(hi) : "l"(in))

// ---------------------------------------------------------------- prep
__global__ void k_init(unsigned long long* deg64, int n) {
    int i = blockIdx.x * blockDim.x + threadIdx.x;
    if (i < n) deg64[i] = (unsigned long long)(1.0f * DEG_FX);  // self-loop, cnt=0
}

// one u64 atomic per edge: count in high bits, fixed-point ew sum in low bits
__global__ void k_hist(const int* __restrict__ dst, const float* __restrict__ ew,
                       unsigned long long* deg64, int ne) {
    int i = blockIdx.x * blockDim.x + threadIdx.x;
    if (i < ne) {
        unsigned long long v = (1ull << CNT_SHIFT)
                             + (unsigned long long)__float2ull_rn(ew[i] * DEG_FX);
        atomicAdd(&deg64[dst[i]], v);
    }
}

// 3-kernel exclusive scan of counts (extracted from deg64) -> off; also writes cnt
__global__ void k_scan1(const unsigned long long* __restrict__ deg64,
                        int* __restrict__ cnt, int* __restrict__ off,
                        int* __restrict__ bsum, int n) {
    __shared__ int ws[32];
    int i = blockIdx.x * 1024 + threadIdx.x;
    int lane = threadIdx.x & 31, w = threadIdx.x >> 5;
    int v = (i < n) ? (int)(__ldg(deg64 + i) >> CNT_SHIFT) : 0;
    if (i < n) cnt[i] = v;
    int incl = v;
    #pragma unroll
    for (int d = 1; d < 32; d <<= 1) {
        int t = __shfl_up_sync(0xffffffffu, incl, d);
        if (lane >= d) incl += t;
    }
    if (lane == 31) ws[w] = incl;
    __syncthreads();
    if (w == 0) {
        int x = ws[lane];
        #pragma unroll
        for (int d = 1; d < 32; d <<= 1) {
            int t = __shfl_up_sync(0xffffffffu, x, d);
            if (lane >= d) x += t;
        }
        ws[lane] = x;
    }
    __syncthreads();
    int wpre = (w == 0) ? 0 : ws[w - 1];
    if (i < n) off[i] = wpre + incl - v;
    if (threadIdx.x == 1023) bsum[blockIdx.x] = ws[31];
}

__global__ void k_scan2(int* bsum, int nb) {
    __shared__ int s[256];
    int t = threadIdx.x;
    s[t] = (t < nb) ? bsum[t] : 0;
    __syncthreads();
    #pragma unroll
    for (int d = 1; d < 256; d <<= 1) {
        int v = (t >= d) ? s[t - d] : 0;
        __syncthreads();
        s[t] += v;
        __syncthreads();
    }
    if (t < nb) bsum[t] = (t == 0) ? 0 : s[t - 1];
}

// finish scan + compute dinv = rsqrt(deg)   (deg >= 1 always: self-loop)
__global__ void k_scan3(int* __restrict__ off, int* __restrict__ cur,
                        const int* __restrict__ bsum,
                        const unsigned long long* __restrict__ deg64,
                        float* __restrict__ dinv, int n) {
    int i = blockIdx.x * blockDim.x + threadIdx.x;
    if (i < n) {
        int o = off[i] + bsum[i >> 10];
        off[i] = o;
        cur[i] = o;
        float d = (float)(__ldg(deg64 + i) & DEG_MASK) * DEG_FX_INV;
        dinv[i] = rsqrtf(d);
    }
}

// place edges: csr[pos] = {src, dinv[src]*ew*dinv[dst]}
__global__ void k_place(const int* __restrict__ src, const int* __restrict__ dst,
                        const float* __restrict__ ew, const float* __restrict__ dinv,
                        int* cur, int2* __restrict__ csr, int ne) {
    int i = blockIdx.x * blockDim.x + threadIdx.x;
    if (i < ne) {
        int s = src[i], d = dst[i];
        int pos = atomicAdd(&cur[d], 1);
        float w = __ldg(dinv + s) * ew[i] * __ldg(dinv + d);
        csr[pos] = make_int2(s, __float_as_int(w));
    }
}

// ---------------------------------------------------------------- GEMM
// Y[n,64] (fp16) = (RELU? max(X,0) : X) @ W[64,64]; 64 rows/block, 4x4 tile, f32x2 FMA
#define SX_STRIDE 68
template<bool RELU>
__global__ void __launch_bounds__(256) k_gemm64(const float* __restrict__ X,
                                                const float* __restrict__ W,
                                                __half* __restrict__ Y, int n) {
    __shared__ float sW[HID * HID];          // 16 KB
    __shared__ float sX[HID * SX_STRIDE];    // 17 KB (padded)
    int tid = threadIdx.x;
    int row0 = blockIdx.x * 64;

    #pragma unroll
    for (int j = 0; j < 4; j++) {
        int vi = tid + j * 256;              // float4 index 0..1023
        float4 wv = __ldg((const float4*)W + vi);
        *(float4*)&sW[vi * 4] = wv;
    }
    #pragma unroll
    for (int j = 0; j < 4; j++) {
        int vi = tid + j * 256;
        int r = vi >> 4;                     // 16 float4 per row
        int c4 = (vi & 15) * 4;
        float4 xv = make_float4(0.f, 0.f, 0.f, 0.f);
        if (row0 + r < n) xv = __ldg((const float4*)(X + (size_t)(row0 + r) * HID + c4));
        if (RELU) {
            xv.x = fmaxf(xv.x, 0.f); xv.y = fmaxf(xv.y, 0.f);
            xv.z = fmaxf(xv.z, 0.f); xv.w = fmaxf(xv.w, 0.f);
        }
        *(float4*)&sX[r * SX_STRIDE + c4] = xv;
    }
    __syncthreads();

    int tx = tid & 15, ty = tid >> 4;
    int c0 = tx * 4, r0 = ty * 4;
    unsigned long long acc[4][2];
    #pragma unroll
    for (int i = 0; i < 4; i++) { acc[i][0] = 0ull; acc[i][1] = 0ull; }

    #pragma unroll 4
    for (int k = 0; k < HID; k++) {
        float4 wv = *(const float4*)&sW[k * HID + c0];
        unsigned long long w01, w23;
        PACK_F32X2(w01, wv.x, wv.y);
        PACK_F32X2(w23, wv.z, wv.w);
        #pragma unroll
        for (int i = 0; i < 4; i++) {
            float x = sX[(r0 + i) * SX_STRIDE + k];
            unsigned long long xp;
            PACK_F32X2(xp, x, x);
            FMA_F32X2(acc[i][0], xp, w01);
            FMA_F32X2(acc[i][1], xp, w23);
        }
    }

    #pragma unroll
    for (int i = 0; i < 4; i++) {
        int r = row0 + r0 + i;
        if (r < n) {
            float4 o;
            UNPACK_F32X2(o.x, o.y, acc[i][0]);
            UNPACK_F32X2(o.z, o.w, acc[i][1]);
            __half2 p01 = __floats2half2_rn(o.x, o.y);
            __half2 p23 = __floats2half2_rn(o.z, o.w);
            uint2 pk;
            pk.x = *(unsigned int*)&p01;
            pk.y = *(unsigned int*)&p23;
            *(uint2*)(Y + (size_t)r * HID + c0) = pk;   // 8B store
        }
    }
}

// ---------------------------------------------------------------- gather
// out[i] = b + h[i]*dinv[i]^2 + sum_{edges into i} w * h[src]   (h in fp16)
// 8 lanes per node (4 nodes per warp): each lane loads uint4 = 8 halves = 16B.
// One LDG.128 serves 4 independent edge chains -> 4x MLP per load instruction.
__global__ void __launch_bounds__(256) k_gather(
    const __half* __restrict__ h, const int2* __restrict__ csr,
    const int* __restrict__ off, const int* __restrict__ cnt,
    const float* __restrict__ dinv, const float* __restrict__ b,
    float* __restrict__ out, int n) {
    int gtid = blockIdx.x * blockDim.x + threadIdx.x;
    int node = gtid >> 3;
    int gl   = gtid & 7;
    if (node >= n) return;
    int beg = __ldg(off + node);
    int deg = __ldg(cnt + node);
    float s = __ldg(dinv + node); s = s * s;

    float acc[8];
    {   // self-loop + bias
        uint4 hp = __ldg((const uint4*)(h + (size_t)node * HID) + gl);
        float2 f0 = __half22float2(*(__half2*)&hp.x);
        float2 f1 = __half22float2(*(__half2*)&hp.y);
        float2 f2 = __half22float2(*(__half2*)&hp.z);
        float2 f3 = __half22float2(*(__half2*)&hp.w);
        float4 bv0 = __ldg((const float4*)b + gl * 2);
        float4 bv1 = __ldg((const float4*)b + gl * 2 + 1);
        acc[0] = fmaf(f0.x, s, bv0.x); acc[1] = fmaf(f0.y, s, bv0.y);
        acc[2] = fmaf(f1.x, s, bv0.z); acc[3] = fmaf(f1.y, s, bv0.w);
        acc[4] = fmaf(f2.x, s, bv1.x); acc[5] = fmaf(f2.y, s, bv1.y);
        acc[6] = fmaf(f3.x, s, bv1.z); acc[7] = fmaf(f3.y, s, bv1.w);
    }

    int j = beg, end = beg + deg, end2 = beg + (deg & ~1);
    for (; j < end2; j += 2) {
        int2 e0 = __ldg(csr + j);
        int2 e1 = __ldg(csr + j + 1);
        uint4 p0 = __ldg((const uint4*)(h + (size_t)e0.x * HID) + gl);
        uint4 p1 = __ldg((const uint4*)(h + (size_t)e1.x * HID) + gl);
        float w0 = __int_as_float(e0.y);
        float w1 = __int_as_float(e1.y);
        float2 a0 = __half22float2(*(__half2*)&p0.x);
        float2 a1 = __half22float2(*(__half2*)&p0.y);
        float2 a2 = __half22float2(*(__half2*)&p0.z);
        float2 a3 = __half22float2(*(__half2*)&p0.w);
        acc[0] = fmaf(a0.x, w0, acc[0]); acc[1] = fmaf(a0.y, w0, acc[1]);
        acc[2] = fmaf(a1.x, w0, acc[2]); acc[3] = fmaf(a1.y, w0, acc[3]);
        acc[4] = fmaf(a2.x, w0, acc[4]); acc[5] = fmaf(a2.y, w0, acc[5]);
        acc[6] = fmaf(a3.x, w0, acc[6]); acc[7] = fmaf(a3.y, w0, acc[7]);
        float2 c0 = __half22float2(*(__half2*)&p1.x);
        float2 c1 = __half22float2(*(__half2*)&p1.y);
        float2 c2 = __half22float2(*(__half2*)&p1.z);
        float2 c3 = __half22float2(*(__half2*)&p1.w);
        acc[0] = fmaf(c0.x, w1, acc[0]); acc[1] = fmaf(c0.y, w1, acc[1]);
        acc[2] = fmaf(c1.x, w1, acc[2]); acc[3] = fmaf(c1.y, w1, acc[3]);
        acc[4] = fmaf(c2.x, w1, acc[4]); acc[5] = fmaf(c2.y, w1, acc[5]);
        acc[6] = fmaf(c3.x, w1, acc[6]); acc[7] = fmaf(c3.y, w1, acc[7]);
    }
    if (j < end) {
        int2 e = __ldg(csr + j);
        uint4 p = __ldg((const uint4*)(h + (size_t)e.x * HID) + gl);
        float w = __int_as_float(e.y);
        float2 a0 = __half22float2(*(__half2*)&p.x);
        float2 a1 = __half22float2(*(__half2*)&p.y);
        float2 a2 = __half22float2(*(__half2*)&p.z);
        float2 a3 = __half22float2(*(__half2*)&p.w);
        acc[0] = fmaf(a0.x, w, acc[0]); acc[1] = fmaf(a0.y, w, acc[1]);
        acc[2] = fmaf(a1.x, w, acc[2]); acc[3] = fmaf(a1.y, w, acc[3]);
        acc[4] = fmaf(a2.x, w, acc[4]); acc[5] = fmaf(a2.y, w, acc[5]);
        acc[6] = fmaf(a3.x, w, acc[6]); acc[7] = fmaf(a3.y, w, acc[7]);
    }

    float* op = out + (size_t)node * HID + gl * 8;
    *(float4*)op       = make_float4(acc[0], acc[1], acc[2], acc[3]);
    *(float4*)(op + 4) = make_float4(acc[4], acc[5], acc[6], acc[7]);
}

// ---------------------------------------------------------------- launch
extern "C" void kernel_launch(void* const* d_in, const int* in_sizes, int n_in,
                              void* d_out, int out_size) {
    const float* x  = (const float*)d_in[0];
    const int*   ei = (const int*)  d_in[1];
    const float* ew = (const float*)d_in[2];
    const float* W1 = (const float*)d_in[3];
    const float* b1 = (const float*)d_in[4];
    const float* W2 = (const float*)d_in[5];
    const float* b2 = (const float*)d_in[6];
    float* out = (float*)d_out;

    int n  = in_sizes[0] / HID;
    int ne = in_sizes[2];
    const int* src = ei;
    const int* dst = ei + ne;

    unsigned long long* deg64;
    float *dinv, *mid;
    __half *h;
    int *cnt, *off, *cur, *bsum;
    int2 *csr;
    cudaGetSymbolAddress((void**)&deg64, g_deg64);
    cudaGetSymbolAddress((void**)&dinv, g_dinv);
    cudaGetSymbolAddress((void**)&cnt,  g_cnt);
    cudaGetSymbolAddress((void**)&off,  g_off);
    cudaGetSymbolAddress((void**)&cur,  g_cur);
    cudaGetSymbolAddress((void**)&bsum, g_bsum);
    cudaGetSymbolAddress((void**)&csr,  g_csr);
    cudaGetSymbolAddress((void**)&h,    g_h);
    cudaGetSymbolAddress((void**)&mid,  g_mid);

    const int T = 256;
    int gn = (n + T - 1) / T;
    int ge = (ne + T - 1) / T;
    int nb = (n + 1023) / 1024;                       // scan blocks (98)
    int gg = (n + 63) / 64;                           // gemm blocks
    int gw = (int)(((size_t)n * 8 + T - 1) / T);      // gather blocks (8 lanes/node)

    // CSR + normalization build (shared by both layers)
    k_init <<<gn, T>>>(deg64, n);
    k_hist <<<ge, T>>>(dst, ew, deg64, ne);
    k_scan1<<<nb, 1024>>>(deg64, cnt, off, bsum, n);
    k_scan2<<<1, 256>>>(bsum, nb);
    k_scan3<<<gn, T>>>(off, cur, bsum, deg64, dinv, n);
    k_place<<<ge, T>>>(src, dst, ew, dinv, cur, csr, ne);

    // layer 1
    k_gemm64<false><<<gg, 256>>>(x, W1, h, n);
    k_gather<<<gw, T>>>(h, csr, off, cnt, dinv, b1, mid, n);

    // layer 2 (relu fused into gemm load)
    k_gemm64<true><<<gg, 256>>>(mid, W2, h, n);
    k_gather<<<gw, T>>>(h, csr, off, cnt, dinv, b2, out, n);
}